// round 2
// baseline (speedup 1.0000x reference)
#include <cuda_runtime.h>
#include <math.h>
#include <stdint.h>

#define EPSF 1e-6f
#define NBATCH 4096
#define RS 132            // padded row stride (transposed layout [K][RS]), mult of 4

// ---------------------------------------------------------------------------
// packed fp32x2 FMA (Blackwell): d = a*b + c elementwise on 2 packed floats
// ---------------------------------------------------------------------------
__device__ __forceinline__ float2 ffma2(float2 a, float2 b, float2 c) {
    float2 d;
    asm("fma.rn.f32x2 %0, %1, %2, %3;"
        : "=l"(reinterpret_cast<unsigned long long&>(d))
        : "l"(reinterpret_cast<unsigned long long&>(a)),
          "l"(reinterpret_cast<unsigned long long&>(b)),
          "l"(reinterpret_cast<unsigned long long&>(c)));
    return d;
}

// Accurate sinf (Cody-Waite, relative-accurate near zeros). |x| <= ~40.
__device__ __forceinline__ float my_sinf(float x) {
    float k = rintf(x * 0.318309886183790672f);
    float r = fmaf(k, -3.14159274101257324f, x);
    r = fmaf(k, 8.742278012618954e-8f, r);
    float r2 = r * r;
    float p = -2.50521083854e-08f;
    p = fmaf(p, r2, 2.75573192239e-06f);
    p = fmaf(p, r2, -1.98412698413e-04f);
    p = fmaf(p, r2, 8.33333333333e-03f);
    p = fmaf(p, r2, -1.66666666667e-01f);
    float s = fmaf(p * r2, r, r);
    int ki = __float2int_rn(k);
    return (ki & 1) ? -s : s;
}

__device__ __forceinline__ float leaky_f(float x) { return x >= 0.f ? x : 0.1f * x; }

// ---------------------------------------------------------------------------
// write one _auge block (50 features) into transposed smem column
// ---------------------------------------------------------------------------
__device__ __forceinline__ void write_aug(float* __restrict__ Acol, int base,
                                          float dx, float dy,
                                          const float* __restrict__ W_s1,
                                          const float* __restrict__ b_s1)
{
    Acol[(base+0)*RS] = dx;
    Acol[(base+1)*RS] = dy;
    #pragma unroll 1
    for (int j = 0; j < 17; j++) {
        float arg = fmaf(dx, __ldg(W_s1 + 2*j),
                    fmaf(dy, __ldg(W_s1 + 2*j + 1), __ldg(b_s1 + j)));
        float s = my_sinf(arg) + EPSF;
        Acol[(base+2+j)*RS]  = s;
        Acol[(base+27+j)*RS] = 1.0f / s;
    }
    float sqx = dx*dx + EPSF, sqy = dy*dy + EPSF;
    float cbx = dx*dx*dx + EPSF, cby = dy*dy*dy + EPSF;
    float exx = expf(dx) + EPSF, exy = expf(dy) + EPSF;
    Acol[(base+19)*RS] = sqx;  Acol[(base+20)*RS] = sqy;
    Acol[(base+21)*RS] = cbx;  Acol[(base+22)*RS] = cby;
    Acol[(base+23)*RS] = exx;  Acol[(base+24)*RS] = exy;
    Acol[(base+25)*RS] = 1.0f / (dx + EPSF);
    Acol[(base+26)*RS] = 1.0f / (dy + EPSF);
    Acol[(base+44)*RS] = 1.0f / sqx;  Acol[(base+45)*RS] = 1.0f / sqy;
    Acol[(base+46)*RS] = 1.0f / cbx;  Acol[(base+47)*RS] = 1.0f / cby;
    Acol[(base+48)*RS] = 1.0f / exx;  Acol[(base+49)*RS] = 1.0f / exy;
}

// ---------------------------------------------------------------------------
// Software-pipelined GEMM tile.
// C_T[o][r] = leaky(b[o] + sum_k A_T[k][r] * W[o][k]) over 128 rows.
// Thread (rt,ot): rt in [0,16) owns contiguous rows 8rt..8rt+7 (4 packed pairs),
// ot owns outs ot*TO..ot*TO+TO-1.
// ---------------------------------------------------------------------------
template<int K, int TO, int LDW>
__device__ __forceinline__ void gemm_tile(const float* __restrict__ At,
                                          const float* __restrict__ Wg,
                                          const float* __restrict__ bg,
                                          float* __restrict__ Ct,
                                          int rt, int ot)
{
    float2 acc[4][TO];
    #pragma unroll
    for (int i = 0; i < TO; i++) {
        float bo = __ldg(bg + ot*TO + i);
        #pragma unroll
        for (int j = 0; j < 4; j++) acc[j][i] = make_float2(bo, bo);
    }
    const float* xb = At + 8*rt;
    const float* wb = Wg + (ot*TO)*LDW;

    // prologue: load k = 0
    float4 xc0 = *reinterpret_cast<const float4*>(xb);
    float4 xc1 = *reinterpret_cast<const float4*>(xb + 4);
    float wc[TO];
    #pragma unroll
    for (int i = 0; i < TO; i++) wc[i] = __ldg(wb + i*LDW);

    #pragma unroll 2
    for (int k = 0; k < K; k++) {
        int kn = (k + 1 < K) ? k + 1 : k;
        // prefetch next k (weights: uniform scalar LDG; x: 2x LDS.128)
        float wn[TO];
        #pragma unroll
        for (int i = 0; i < TO; i++) wn[i] = __ldg(wb + i*LDW + kn);
        float4 xn0 = *reinterpret_cast<const float4*>(xb + kn*RS);
        float4 xn1 = *reinterpret_cast<const float4*>(xb + kn*RS + 4);

        // compute current k: 4*TO packed fmas
        float2 p0 = make_float2(xc0.x, xc0.y);
        float2 p1 = make_float2(xc0.z, xc0.w);
        float2 p2 = make_float2(xc1.x, xc1.y);
        float2 p3 = make_float2(xc1.z, xc1.w);
        #pragma unroll
        for (int i = 0; i < TO; i++) {
            float2 ws = make_float2(wc[i], wc[i]);
            acc[0][i] = ffma2(p0, ws, acc[0][i]);
            acc[1][i] = ffma2(p1, ws, acc[1][i]);
            acc[2][i] = ffma2(p2, ws, acc[2][i]);
            acc[3][i] = ffma2(p3, ws, acc[3][i]);
        }
        xc0 = xn0; xc1 = xn1;
        #pragma unroll
        for (int i = 0; i < TO; i++) wc[i] = wn[i];
    }

    // epilogue: leaky + contiguous float4 stores
    #pragma unroll
    for (int i = 0; i < TO; i++) {
        float4 v0, v1;
        v0.x = leaky_f(acc[0][i].x); v0.y = leaky_f(acc[0][i].y);
        v0.z = leaky_f(acc[1][i].x); v0.w = leaky_f(acc[1][i].y);
        v1.x = leaky_f(acc[2][i].x); v1.y = leaky_f(acc[2][i].y);
        v1.z = leaky_f(acc[3][i].x); v1.w = leaky_f(acc[3][i].y);
        float* cb = Ct + (ot*TO + i)*RS + 8*rt;
        *reinterpret_cast<float4*>(cb)     = v0;
        *reinterpret_cast<float4*>(cb + 4) = v1;
    }
}

// smem layout (floats): region0 [128][RS] (features A_T[114][RS], later h2_T),
// region1 h1_T[256][RS], then en[128][2], logits[128]
#define SM_R0   (128*RS)
#define SM_R1   (256*RS)
#define SM_EN   (SM_R0 + SM_R1)
#define SM_LG   (SM_EN + 256)
#define SM_TOT  (SM_LG + 128)

#define EN_BLOCKS (NBATCH/2)

__global__ void __launch_bounds__(512, 1)
fused_kernel(const float* __restrict__ ego_y,
             const float* __restrict__ Pn,  const float* __restrict__ Pego,
             const float* __restrict__ Vn,  const float* __restrict__ Vego,
             const float* __restrict__ Cn,
             const float* __restrict__ W_sel, const float* __restrict__ b_sel,
             const float* __restrict__ W_s0,  const float* __restrict__ b_s0,
             const float* __restrict__ W_map, const float* __restrict__ b_map,
             const float* __restrict__ W_efc, const float* __restrict__ b_efc,
             const float* __restrict__ W_s1, const float* __restrict__ b_s1,
             const float* __restrict__ W1,  const float* __restrict__ b1,
             const float* __restrict__ W2,  const float* __restrict__ b2,
             const float* __restrict__ W3,  const float* __restrict__ b3,
             const float* __restrict__ Ww,  const float* __restrict__ bw,
             float* __restrict__ out)
{
    extern __shared__ float sm[];
    int tid = threadIdx.x;
    int blk = blockIdx.x;

    // =======================================================================
    // Er head blocks
    // =======================================================================
    if (blk >= EN_BLOCKS) {
        if (tid < 256) {
            int b = (blk - EN_BLOCKS) * 256 + tid;
            float ey = ego_y[b];
            float dy[4] = { 13.55f - ey, 17.45f - ey, 21.12f - ey, 24.91f - ey };

            float z[4];
            #pragma unroll
            for (int o = 0; o < 4; o++) {
                float a = __ldg(b_sel + o);
                #pragma unroll
                for (int i = 0; i < 4; i++) a = fmaf(dy[i], __ldg(W_sel + o*4+i), a);
                z[o] = a;
            }
            float m = fmaxf(fmaxf(z[0], z[1]), fmaxf(z[2], z[3]));
            float e[4], ssum = 0.f;
            #pragma unroll
            for (int i = 0; i < 4; i++) { e[i] = expf(z[i] - m); ssum += e[i]; }
            float x[4];
            #pragma unroll
            for (int i = 0; i < 4; i++) x[i] = (e[i] / ssum) * dy[i];

            float f[48];
            #pragma unroll
            for (int i = 0; i < 4; i++) f[i] = x[i];
            #pragma unroll
            for (int j = 0; j < 8; j++) {
                float arg = __ldg(b_s0 + j);
                #pragma unroll
                for (int i = 0; i < 4; i++) arg = fmaf(x[i], __ldg(W_s0 + j*4+i), arg);
                float s = my_sinf(arg) + EPSF;
                f[4 + j] = s;
                f[28 + j] = 1.0f / s;
            }
            #pragma unroll
            for (int i = 0; i < 4; i++) {
                float sq = x[i]*x[i] + EPSF;
                float cb = x[i]*x[i]*x[i] + EPSF;
                float ex = expf(x[i]) + EPSF;
                f[12+i] = sq;           f[36+i] = 1.0f / sq;
                f[16+i] = cb;           f[40+i] = 1.0f / cb;
                f[20+i] = ex;           f[44+i] = 1.0f / ex;
                f[24+i] = 1.0f / (x[i] + EPSF);
            }
            float y[8];
            #pragma unroll
            for (int o = 0; o < 8; o++) {
                float a = __ldg(b_map + o);
                #pragma unroll
                for (int k = 0; k < 48; k++) a = fmaf(f[k], __ldg(W_map + o*48+k), a);
                y[o] = leaky_f(a);
            }
            float r0 = __ldg(b_efc), r1 = __ldg(b_efc + 1);
            #pragma unroll
            for (int k = 0; k < 8; k++) {
                r0 = fmaf(y[k], __ldg(W_efc + k),     r0);
                r1 = fmaf(y[k], __ldg(W_efc + 8 + k), r1);
            }
            out[b*4 + 0] = r0;
            out[b*4 + 1] = r1;
        }
        return;
    }

    // =======================================================================
    // En blocks: 128 rows (2 batches x 64 neighbors)
    // =======================================================================
    float* At  = sm;              // features (transposed), later h2_T
    float* h1T = sm + SM_R0;
    float* enb = sm + SM_EN;
    float* lgb = sm + SM_LG;

    // ---- phase 0: features, 2 threads per row (P-part / V-part) ----
    if (tid < 256) {
        int r = tid >> 1;
        int part = tid & 1;
        int b = blk*2 + (r >> 6);
        int n = r & 63;
        int idx2 = (b*64 + n) * 2;
        float* Acol = At + r;
        if (part == 0) {
            float pex = Pego[b*2], pey = Pego[b*2+1];
            float pnx = Pn[idx2],  pny = Pn[idx2+1];
            float dx = pnx - pex,  dy = pny - pey;
            Acol[0*RS] = pex;  Acol[1*RS] = pey;
            Acol[2*RS] = pnx;  Acol[3*RS] = pny;
            Acol[4*RS] = dx;   Acol[5*RS] = dy;
            write_aug(Acol, 6, dx, dy, W_s1, b_s1);
            Acol[112*RS] = Cn[idx2];
            Acol[113*RS] = Cn[idx2+1];
        } else {
            float vex = Vego[b*2], vey = Vego[b*2+1];
            float vnx = Vn[idx2],  vny = Vn[idx2+1];
            float dx = vnx - vex,  dy = vny - vey;
            Acol[56*RS] = vex;  Acol[57*RS] = vey;
            Acol[58*RS] = vnx;  Acol[59*RS] = vny;
            Acol[60*RS] = dx;   Acol[61*RS] = dy;
            write_aug(Acol, 62, dx, dy, W_s1, b_s1);
        }
    }
    __syncthreads();

    int rt = tid & 15;
    int ot = tid >> 4;

    // ---- layer1: [128,114] -> [128,256], leaky ----
    gemm_tile<114, 8, 114>(At, W1, b1, h1T, rt, ot);
    __syncthreads();

    // ---- layer2: [128,256] -> [128,128], leaky (writes into At region) ----
    gemm_tile<256, 4, 256>(h1T, W2, b2, At, rt, ot);
    __syncthreads();

    // ---- layer3 + logits ----
    if (tid < 128) {
        int r = tid;
        float a0 = __ldg(b3), a1 = __ldg(b3 + 1);
        #pragma unroll 4
        for (int k = 0; k < 128; k++) {
            float h = At[k*RS + r];
            a0 = fmaf(h, __ldg(W3 + k),       a0);
            a1 = fmaf(h, __ldg(W3 + 128 + k), a1);
        }
        enb[r*2]   = a0;
        enb[r*2+1] = a1;
        int b = blk*2 + (r >> 6);
        int n = r & 63;
        int idx2 = (b*64 + n) * 2;
        float pnx = Pn[idx2], pny = Pn[idx2+1];
        float dx = pnx - Pego[b*2], dy = pny - Pego[b*2+1];
        float lg = __ldg(bw);
        lg = fmaf(__ldg(Ww+0), a0,  lg);
        lg = fmaf(__ldg(Ww+1), a1,  lg);
        lg = fmaf(__ldg(Ww+2), pnx, lg);
        lg = fmaf(__ldg(Ww+3), pny, lg);
        lg = fmaf(__ldg(Ww+4), dx,  lg);
        lg = fmaf(__ldg(Ww+5), dy,  lg);
        lgb[r] = lg;
    }
    __syncthreads();

    // ---- softmax over 64 neighbors + weighted sum ----
    if (tid < 64) {
        int w = tid >> 5, l = tid & 31;
        int base = w * 64;
        float v0 = lgb[base + l], v1 = lgb[base + 32 + l];
        float m = fmaxf(v0, v1);
        #pragma unroll
        for (int off = 16; off; off >>= 1)
            m = fmaxf(m, __shfl_xor_sync(0xffffffffu, m, off));
        float e0 = expf(v0 - m), e1 = expf(v1 - m);
        float s  = e0 + e1;
        float n0 = e0 * enb[(base+l)*2]     + e1 * enb[(base+32+l)*2];
        float n1 = e0 * enb[(base+l)*2 + 1] + e1 * enb[(base+32+l)*2 + 1];
        #pragma unroll
        for (int off = 16; off; off >>= 1) {
            s  += __shfl_xor_sync(0xffffffffu, s,  off);
            n0 += __shfl_xor_sync(0xffffffffu, n0, off);
            n1 += __shfl_xor_sync(0xffffffffu, n1, off);
        }
        if (l == 0) {
            int b = blk*2 + w;
            out[b*4 + 2] = n0 / s;
            out[b*4 + 3] = n1 / s;
        }
    }
}

// ---------------------------------------------------------------------------
extern "C" void kernel_launch(void* const* d_in, const int* in_sizes, int n_in,
                              void* d_out, int out_size)
{
    const float* ego_y = (const float*)d_in[0];
    const float* Pn    = (const float*)d_in[1];
    const float* Pego  = (const float*)d_in[2];
    const float* Vn    = (const float*)d_in[3];
    const float* Vego  = (const float*)d_in[4];
    const float* Cn    = (const float*)d_in[5];
    const float* W_sel = (const float*)d_in[6];
    const float* b_sel = (const float*)d_in[7];
    const float* W_s0  = (const float*)d_in[8];
    const float* b_s0  = (const float*)d_in[9];
    const float* W_map = (const float*)d_in[10];
    const float* b_map = (const float*)d_in[11];
    const float* W_efc = (const float*)d_in[12];
    const float* b_efc = (const float*)d_in[13];
    const float* W_s1  = (const float*)d_in[14];
    const float* b_s1  = (const float*)d_in[15];
    const float* W1    = (const float*)d_in[16];
    const float* b1    = (const float*)d_in[17];
    const float* W2    = (const float*)d_in[18];
    const float* b2    = (const float*)d_in[19];
    const float* W3    = (const float*)d_in[20];
    const float* b3    = (const float*)d_in[21];
    const float* Ww    = (const float*)d_in[22];
    const float* bw    = (const float*)d_in[23];
    float* out = (float*)d_out;

    size_t smem_bytes = (size_t)SM_TOT * sizeof(float);
    cudaFuncSetAttribute(fused_kernel, cudaFuncAttributeMaxDynamicSharedMemorySize,
                         (int)smem_bytes);

    fused_kernel<<<EN_BLOCKS + 16, 512, smem_bytes>>>(
        ego_y, Pn, Pego, Vn, Vego, Cn,
        W_sel, b_sel, W_s0, b_s0, W_map, b_map, W_efc, b_efc,
        W_s1, b_s1, W1, b1, W2, b2, W3, b3, Ww, bw, out);
}

// round 3
// speedup vs baseline: 1.1845x; 1.1845x over previous
#include <cuda_runtime.h>
#include <math.h>
#include <stdint.h>

#define EPSF 1e-6f
#define NBATCH 4096
#define RS 132            // padded row stride (transposed layout [K][RS]), mult of 4

// ---------------------------------------------------------------------------
// packed fp32x2 FMA (Blackwell): d = a*b + c elementwise on 2 packed floats
// ---------------------------------------------------------------------------
__device__ __forceinline__ float2 ffma2(float2 a, float2 b, float2 c) {
    float2 d;
    asm("fma.rn.f32x2 %0, %1, %2, %3;"
        : "=l"(reinterpret_cast<unsigned long long&>(d))
        : "l"(reinterpret_cast<unsigned long long&>(a)),
          "l"(reinterpret_cast<unsigned long long&>(b)),
          "l"(reinterpret_cast<unsigned long long&>(c)));
    return d;
}

// Accurate sinf (Cody-Waite, relative-accurate near zeros). |x| <= ~40.
__device__ __forceinline__ float my_sinf(float x) {
    float k = rintf(x * 0.318309886183790672f);
    float r = fmaf(k, -3.14159274101257324f, x);
    r = fmaf(k, 8.742278012618954e-8f, r);
    float r2 = r * r;
    float p = -2.50521083854e-08f;
    p = fmaf(p, r2, 2.75573192239e-06f);
    p = fmaf(p, r2, -1.98412698413e-04f);
    p = fmaf(p, r2, 8.33333333333e-03f);
    p = fmaf(p, r2, -1.66666666667e-01f);
    float s = fmaf(p * r2, r, r);
    int ki = __float2int_rn(k);
    return (ki & 1) ? -s : s;
}

__device__ __forceinline__ float leaky_f(float x) { return x >= 0.f ? x : 0.1f * x; }

// ---------------------------------------------------------------------------
// write one _auge block (50 features) into transposed smem column
// ---------------------------------------------------------------------------
__device__ __forceinline__ void write_aug(float* __restrict__ Acol, int base,
                                          float dx, float dy,
                                          const float* __restrict__ W_s1,
                                          const float* __restrict__ b_s1)
{
    Acol[(base+0)*RS] = dx;
    Acol[(base+1)*RS] = dy;
    #pragma unroll 1
    for (int j = 0; j < 17; j++) {
        float arg = fmaf(dx, __ldg(W_s1 + 2*j),
                    fmaf(dy, __ldg(W_s1 + 2*j + 1), __ldg(b_s1 + j)));
        float s = my_sinf(arg) + EPSF;
        Acol[(base+2+j)*RS]  = s;
        Acol[(base+27+j)*RS] = 1.0f / s;
    }
    float sqx = dx*dx + EPSF, sqy = dy*dy + EPSF;
    float cbx = dx*dx*dx + EPSF, cby = dy*dy*dy + EPSF;
    float exx = expf(dx) + EPSF, exy = expf(dy) + EPSF;
    Acol[(base+19)*RS] = sqx;  Acol[(base+20)*RS] = sqy;
    Acol[(base+21)*RS] = cbx;  Acol[(base+22)*RS] = cby;
    Acol[(base+23)*RS] = exx;  Acol[(base+24)*RS] = exy;
    Acol[(base+25)*RS] = 1.0f / (dx + EPSF);
    Acol[(base+26)*RS] = 1.0f / (dy + EPSF);
    Acol[(base+44)*RS] = 1.0f / sqx;  Acol[(base+45)*RS] = 1.0f / sqy;
    Acol[(base+46)*RS] = 1.0f / cbx;  Acol[(base+47)*RS] = 1.0f / cby;
    Acol[(base+48)*RS] = 1.0f / exx;  Acol[(base+49)*RS] = 1.0f / exy;
}

// ---------------------------------------------------------------------------
// GEMM tile with register double-buffered weights (float2 per 2 k-steps).
// C_T[o][r] = leaky(b[o] + sum_k A_T[k][r] * W[o][k]) over 128 rows.
// Thread (rt,ot): rt in [0,16) owns contiguous rows 8rt..8rt+7 (4 packed pairs),
// ot owns outs ot*TO..ot*TO+TO-1.
// ---------------------------------------------------------------------------
template<int K, int TO, int LDW>
__device__ __forceinline__ void gemm_tile(const float* __restrict__ At,
                                          const float* __restrict__ Wg,
                                          const float* __restrict__ bg,
                                          float* __restrict__ Ct,
                                          int rt, int ot)
{
    float2 acc[4][TO];
    #pragma unroll
    for (int i = 0; i < TO; i++) {
        float bo = __ldg(bg + ot*TO + i);
        #pragma unroll
        for (int j = 0; j < 4; j++) acc[j][i] = make_float2(bo, bo);
    }
    const float* xb = At + 8*rt;
    const float* wb = Wg + (ot*TO)*LDW;

    // prologue: weights for k={0,1}
    float2 wc[TO];
    #pragma unroll
    for (int i = 0; i < TO; i++)
        wc[i] = __ldg(reinterpret_cast<const float2*>(wb + i*LDW));

    #pragma unroll 1
    for (int k = 0; k < K; k += 2) {
        // x for k and k+1 (4x LDS.128) — consumed ~10 instrs later
        float4 x0a = *reinterpret_cast<const float4*>(xb + k*RS);
        float4 x0b = *reinterpret_cast<const float4*>(xb + k*RS + 4);
        float4 x1a = *reinterpret_cast<const float4*>(xb + (k+1)*RS);
        float4 x1b = *reinterpret_cast<const float4*>(xb + (k+1)*RS + 4);

        // prefetch weights for k+2 (full iteration ahead)
        int kn = (k + 2 < K) ? k + 2 : 0;
        float2 wn[TO];
        #pragma unroll
        for (int i = 0; i < TO; i++)
            wn[i] = __ldg(reinterpret_cast<const float2*>(wb + i*LDW + kn));

        float2 p0 = make_float2(x0a.x, x0a.y);
        float2 p1 = make_float2(x0a.z, x0a.w);
        float2 p2 = make_float2(x0b.x, x0b.y);
        float2 p3 = make_float2(x0b.z, x0b.w);
        float2 q0 = make_float2(x1a.x, x1a.y);
        float2 q1 = make_float2(x1a.z, x1a.w);
        float2 q2 = make_float2(x1b.x, x1b.y);
        float2 q3 = make_float2(x1b.z, x1b.w);

        #pragma unroll
        for (int i = 0; i < TO; i++) {
            float2 wa = make_float2(wc[i].x, wc[i].x);
            acc[0][i] = ffma2(p0, wa, acc[0][i]);
            acc[1][i] = ffma2(p1, wa, acc[1][i]);
            acc[2][i] = ffma2(p2, wa, acc[2][i]);
            acc[3][i] = ffma2(p3, wa, acc[3][i]);
            float2 wv = make_float2(wc[i].y, wc[i].y);
            acc[0][i] = ffma2(q0, wv, acc[0][i]);
            acc[1][i] = ffma2(q1, wv, acc[1][i]);
            acc[2][i] = ffma2(q2, wv, acc[2][i]);
            acc[3][i] = ffma2(q3, wv, acc[3][i]);
        }
        #pragma unroll
        for (int i = 0; i < TO; i++) wc[i] = wn[i];
    }

    // epilogue: leaky + contiguous float4 stores
    #pragma unroll
    for (int i = 0; i < TO; i++) {
        float4 v0, v1;
        v0.x = leaky_f(acc[0][i].x); v0.y = leaky_f(acc[0][i].y);
        v0.z = leaky_f(acc[1][i].x); v0.w = leaky_f(acc[1][i].y);
        v1.x = leaky_f(acc[2][i].x); v1.y = leaky_f(acc[2][i].y);
        v1.z = leaky_f(acc[3][i].x); v1.w = leaky_f(acc[3][i].y);
        float* cb = Ct + (ot*TO + i)*RS + 8*rt;
        *reinterpret_cast<float4*>(cb)     = v0;
        *reinterpret_cast<float4*>(cb + 4) = v1;
    }
}

// smem layout (floats): region0 [128][RS] (features A_T[114][RS], later h2_T),
// region1 h1_T[256][RS] (scratch for layer3 partials afterwards),
// then en[128][2], logits[128]
#define SM_R0   (128*RS)
#define SM_R1   (256*RS)
#define SM_EN   (SM_R0 + SM_R1)
#define SM_LG   (SM_EN + 256)
#define SM_TOT  (SM_LG + 128)

#define EN_BLOCKS (NBATCH/2)

__global__ void __launch_bounds__(512, 1)
fused_kernel(const float* __restrict__ ego_y,
             const float* __restrict__ Pn,  const float* __restrict__ Pego,
             const float* __restrict__ Vn,  const float* __restrict__ Vego,
             const float* __restrict__ Cn,
             const float* __restrict__ W_sel, const float* __restrict__ b_sel,
             const float* __restrict__ W_s0,  const float* __restrict__ b_s0,
             const float* __restrict__ W_map, const float* __restrict__ b_map,
             const float* __restrict__ W_efc, const float* __restrict__ b_efc,
             const float* __restrict__ W_s1, const float* __restrict__ b_s1,
             const float* __restrict__ W1,  const float* __restrict__ b1,
             const float* __restrict__ W2,  const float* __restrict__ b2,
             const float* __restrict__ W3,  const float* __restrict__ b3,
             const float* __restrict__ Ww,  const float* __restrict__ bw,
             float* __restrict__ out)
{
    extern __shared__ float sm[];
    int tid = threadIdx.x;
    int blk = blockIdx.x;

    // =======================================================================
    // Er head blocks
    // =======================================================================
    if (blk >= EN_BLOCKS) {
        if (tid < 256) {
            int b = (blk - EN_BLOCKS) * 256 + tid;
            float ey = ego_y[b];
            float dy[4] = { 13.55f - ey, 17.45f - ey, 21.12f - ey, 24.91f - ey };

            float z[4];
            #pragma unroll
            for (int o = 0; o < 4; o++) {
                float a = __ldg(b_sel + o);
                #pragma unroll
                for (int i = 0; i < 4; i++) a = fmaf(dy[i], __ldg(W_sel + o*4+i), a);
                z[o] = a;
            }
            float m = fmaxf(fmaxf(z[0], z[1]), fmaxf(z[2], z[3]));
            float e[4], ssum = 0.f;
            #pragma unroll
            for (int i = 0; i < 4; i++) { e[i] = expf(z[i] - m); ssum += e[i]; }
            float x[4];
            #pragma unroll
            for (int i = 0; i < 4; i++) x[i] = (e[i] / ssum) * dy[i];

            float f[48];
            #pragma unroll
            for (int i = 0; i < 4; i++) f[i] = x[i];
            #pragma unroll
            for (int j = 0; j < 8; j++) {
                float arg = __ldg(b_s0 + j);
                #pragma unroll
                for (int i = 0; i < 4; i++) arg = fmaf(x[i], __ldg(W_s0 + j*4+i), arg);
                float s = my_sinf(arg) + EPSF;
                f[4 + j] = s;
                f[28 + j] = 1.0f / s;
            }
            #pragma unroll
            for (int i = 0; i < 4; i++) {
                float sq = x[i]*x[i] + EPSF;
                float cb = x[i]*x[i]*x[i] + EPSF;
                float ex = expf(x[i]) + EPSF;
                f[12+i] = sq;           f[36+i] = 1.0f / sq;
                f[16+i] = cb;           f[40+i] = 1.0f / cb;
                f[20+i] = ex;           f[44+i] = 1.0f / ex;
                f[24+i] = 1.0f / (x[i] + EPSF);
            }
            float y[8];
            #pragma unroll
            for (int o = 0; o < 8; o++) {
                float a = __ldg(b_map + o);
                #pragma unroll
                for (int k = 0; k < 48; k++) a = fmaf(f[k], __ldg(W_map + o*48+k), a);
                y[o] = leaky_f(a);
            }
            float r0 = __ldg(b_efc), r1 = __ldg(b_efc + 1);
            #pragma unroll
            for (int k = 0; k < 8; k++) {
                r0 = fmaf(y[k], __ldg(W_efc + k),     r0);
                r1 = fmaf(y[k], __ldg(W_efc + 8 + k), r1);
            }
            out[b*4 + 0] = r0;
            out[b*4 + 1] = r1;
        }
        return;
    }

    // =======================================================================
    // En blocks: 128 rows (2 batches x 64 neighbors)
    // =======================================================================
    float* At  = sm;              // features (transposed), later h2_T
    float* h1T = sm + SM_R0;      // h1, then layer3 partial scratch
    float* enb = sm + SM_EN;
    float* lgb = sm + SM_LG;

    // ---- phase 0: features, 2 threads per row (P-part / V-part) ----
    if (tid < 256) {
        int r = tid >> 1;
        int part = tid & 1;
        int b = blk*2 + (r >> 6);
        int n = r & 63;
        int idx2 = (b*64 + n) * 2;
        float* Acol = At + r;
        if (part == 0) {
            float pex = Pego[b*2], pey = Pego[b*2+1];
            float pnx = Pn[idx2],  pny = Pn[idx2+1];
            float dx = pnx - pex,  dy = pny - pey;
            Acol[0*RS] = pex;  Acol[1*RS] = pey;
            Acol[2*RS] = pnx;  Acol[3*RS] = pny;
            Acol[4*RS] = dx;   Acol[5*RS] = dy;
            write_aug(Acol, 6, dx, dy, W_s1, b_s1);
            Acol[112*RS] = Cn[idx2];
            Acol[113*RS] = Cn[idx2+1];
        } else {
            float vex = Vego[b*2], vey = Vego[b*2+1];
            float vnx = Vn[idx2],  vny = Vn[idx2+1];
            float dx = vnx - vex,  dy = vny - vey;
            Acol[56*RS] = vex;  Acol[57*RS] = vey;
            Acol[58*RS] = vnx;  Acol[59*RS] = vny;
            Acol[60*RS] = dx;   Acol[61*RS] = dy;
            write_aug(Acol, 62, dx, dy, W_s1, b_s1);
        }
    }
    __syncthreads();

    int rt = tid & 15;
    int ot = tid >> 4;

    // ---- layer1: [128,114] -> [128,256], leaky ----
    gemm_tile<114, 8, 114>(At, W1, b1, h1T, rt, ot);
    __syncthreads();

    // ---- layer2: [128,256] -> [128,128], leaky (writes into At region) ----
    gemm_tile<256, 4, 256>(h1T, W2, b2, At, rt, ot);
    __syncthreads();

    // ---- layer3: all 512 threads (4 k-segments x 128 rows), partials in smem
    {
        int seg = tid >> 7;        // 0..3
        int r   = tid & 127;
        int k0  = seg * 32;
        float a0 = 0.f, a1 = 0.f;
        #pragma unroll 8
        for (int k = k0; k < k0 + 32; k++) {
            float h = At[k*RS + r];
            a0 = fmaf(h, __ldg(W3 + k),       a0);
            a1 = fmaf(h, __ldg(W3 + 128 + k), a1);
        }
        h1T[(seg*128 + r)*2]     = a0;
        h1T[(seg*128 + r)*2 + 1] = a1;
    }
    __syncthreads();

    // ---- layer3 reduce + logits ----
    if (tid < 128) {
        int r = tid;
        float a0 = __ldg(b3), a1 = __ldg(b3 + 1);
        #pragma unroll
        for (int seg = 0; seg < 4; seg++) {
            a0 += h1T[(seg*128 + r)*2];
            a1 += h1T[(seg*128 + r)*2 + 1];
        }
        enb[r*2]   = a0;
        enb[r*2+1] = a1;
        int b = blk*2 + (r >> 6);
        int n = r & 63;
        int idx2 = (b*64 + n) * 2;
        float pnx = Pn[idx2], pny = Pn[idx2+1];
        float dx = pnx - Pego[b*2], dy = pny - Pego[b*2+1];
        float lg = __ldg(bw);
        lg = fmaf(__ldg(Ww+0), a0,  lg);
        lg = fmaf(__ldg(Ww+1), a1,  lg);
        lg = fmaf(__ldg(Ww+2), pnx, lg);
        lg = fmaf(__ldg(Ww+3), pny, lg);
        lg = fmaf(__ldg(Ww+4), dx,  lg);
        lg = fmaf(__ldg(Ww+5), dy,  lg);
        lgb[r] = lg;
    }
    __syncthreads();

    // ---- softmax over 64 neighbors + weighted sum ----
    if (tid < 64) {
        int w = tid >> 5, l = tid & 31;
        int base = w * 64;
        float v0 = lgb[base + l], v1 = lgb[base + 32 + l];
        float m = fmaxf(v0, v1);
        #pragma unroll
        for (int off = 16; off; off >>= 1)
            m = fmaxf(m, __shfl_xor_sync(0xffffffffu, m, off));
        float e0 = expf(v0 - m), e1 = expf(v1 - m);
        float s  = e0 + e1;
        float n0 = e0 * enb[(base+l)*2]     + e1 * enb[(base+32+l)*2];
        float n1 = e0 * enb[(base+l)*2 + 1] + e1 * enb[(base+32+l)*2 + 1];
        #pragma unroll
        for (int off = 16; off; off >>= 1) {
            s  += __shfl_xor_sync(0xffffffffu, s,  off);
            n0 += __shfl_xor_sync(0xffffffffu, n0, off);
            n1 += __shfl_xor_sync(0xffffffffu, n1, off);
        }
        if (l == 0) {
            int b = blk*2 + w;
            out[b*4 + 2] = n0 / s;
            out[b*4 + 3] = n1 / s;
        }
    }
}

// ---------------------------------------------------------------------------
extern "C" void kernel_launch(void* const* d_in, const int* in_sizes, int n_in,
                              void* d_out, int out_size)
{
    const float* ego_y = (const float*)d_in[0];
    const float* Pn    = (const float*)d_in[1];
    const float* Pego  = (const float*)d_in[2];
    const float* Vn    = (const float*)d_in[3];
    const float* Vego  = (const float*)d_in[4];
    const float* Cn    = (const float*)d_in[5];
    const float* W_sel = (const float*)d_in[6];
    const float* b_sel = (const float*)d_in[7];
    const float* W_s0  = (const float*)d_in[8];
    const float* b_s0  = (const float*)d_in[9];
    const float* W_map = (const float*)d_in[10];
    const float* b_map = (const float*)d_in[11];
    const float* W_efc = (const float*)d_in[12];
    const float* b_efc = (const float*)d_in[13];
    const float* W_s1  = (const float*)d_in[14];
    const float* b_s1  = (const float*)d_in[15];
    const float* W1    = (const float*)d_in[16];
    const float* b1    = (const float*)d_in[17];
    const float* W2    = (const float*)d_in[18];
    const float* b2    = (const float*)d_in[19];
    const float* W3    = (const float*)d_in[20];
    const float* b3    = (const float*)d_in[21];
    const float* Ww    = (const float*)d_in[22];
    const float* bw    = (const float*)d_in[23];
    float* out = (float*)d_out;

    size_t smem_bytes = (size_t)SM_TOT * sizeof(float);
    cudaFuncSetAttribute(fused_kernel, cudaFuncAttributeMaxDynamicSharedMemorySize,
                         (int)smem_bytes);

    fused_kernel<<<EN_BLOCKS + 16, 512, smem_bytes>>>(
        ego_y, Pn, Pego, Vn, Vego, Cn,
        W_sel, b_sel, W_s0, b_s0, W_map, b_map, W_efc, b_efc,
        W_s1, b_s1, W1, b1, W2, b2, W3, b3, Ww, bw, out);
}

// round 4
// speedup vs baseline: 1.5252x; 1.2876x over previous
#include <cuda_runtime.h>
#include <math.h>
#include <stdint.h>

#define EPSF 1e-6f
#define NBATCH 4096
#define RS 132            // padded row stride (layout [k][row]), mult of 4

// k-major repacked weights
__device__ float g_W1c[114 * 256];   // [k][out]
__device__ float g_W2c[256 * 128];   // [k][out]

// ---------------------------------------------------------------------------
__device__ __forceinline__ float2 ffma2(float2 a, float2 b, float2 c) {
    float2 d;
    asm("fma.rn.f32x2 %0, %1, %2, %3;"
        : "=l"(reinterpret_cast<unsigned long long&>(d))
        : "l"(reinterpret_cast<unsigned long long&>(a)),
          "l"(reinterpret_cast<unsigned long long&>(b)),
          "l"(reinterpret_cast<unsigned long long&>(c)));
    return d;
}

__device__ __forceinline__ float my_sinf(float x) {
    float k = rintf(x * 0.318309886183790672f);
    float r = fmaf(k, -3.14159274101257324f, x);
    r = fmaf(k, 8.742278012618954e-8f, r);
    float r2 = r * r;
    float p = -2.50521083854e-08f;
    p = fmaf(p, r2, 2.75573192239e-06f);
    p = fmaf(p, r2, -1.98412698413e-04f);
    p = fmaf(p, r2, 8.33333333333e-03f);
    p = fmaf(p, r2, -1.66666666667e-01f);
    float s = fmaf(p * r2, r, r);
    int ki = __float2int_rn(k);
    return (ki & 1) ? -s : s;
}

__device__ __forceinline__ float leaky_f(float x) { return x >= 0.f ? x : 0.1f * x; }

// ---------------------------------------------------------------------------
// repack W1 [256,114] -> W1c [114,256]; W2 [128,256] -> W2c [256,128]
// ---------------------------------------------------------------------------
__global__ void repack_kernel(const float* __restrict__ W1,
                              const float* __restrict__ W2)
{
    int idx = blockIdx.x * 256 + threadIdx.x;
    if (idx < 114 * 256) {
        int k = idx >> 8, o = idx & 255;
        g_W1c[idx] = W1[o * 114 + k];
    }
    if (idx < 256 * 128) {
        int k = idx >> 7, o = idx & 127;
        g_W2c[idx] = W2[o * 256 + k];
    }
}

// ---------------------------------------------------------------------------
// write one _auge block (50 features) into transposed smem column
// ---------------------------------------------------------------------------
__device__ __forceinline__ void write_aug(float* __restrict__ Acol, int base,
                                          float dx, float dy,
                                          const float* __restrict__ W_s1,
                                          const float* __restrict__ b_s1)
{
    Acol[(base+0)*RS] = dx;
    Acol[(base+1)*RS] = dy;
    #pragma unroll 1
    for (int j = 0; j < 17; j++) {
        float arg = fmaf(dx, __ldg(W_s1 + 2*j),
                    fmaf(dy, __ldg(W_s1 + 2*j + 1), __ldg(b_s1 + j)));
        float s = my_sinf(arg) + EPSF;
        Acol[(base+2+j)*RS]  = s;
        Acol[(base+27+j)*RS] = 1.0f / s;
    }
    float sqx = dx*dx + EPSF, sqy = dy*dy + EPSF;
    float cbx = dx*dx*dx + EPSF, cby = dy*dy*dy + EPSF;
    float exx = expf(dx) + EPSF, exy = expf(dy) + EPSF;
    Acol[(base+19)*RS] = sqx;  Acol[(base+20)*RS] = sqy;
    Acol[(base+21)*RS] = cbx;  Acol[(base+22)*RS] = cby;
    Acol[(base+23)*RS] = exx;  Acol[(base+24)*RS] = exy;
    Acol[(base+25)*RS] = 1.0f / (dx + EPSF);
    Acol[(base+26)*RS] = 1.0f / (dy + EPSF);
    Acol[(base+44)*RS] = 1.0f / sqx;  Acol[(base+45)*RS] = 1.0f / sqy;
    Acol[(base+46)*RS] = 1.0f / cbx;  Acol[(base+47)*RS] = 1.0f / cby;
    Acol[(base+48)*RS] = 1.0f / exx;  Acol[(base+49)*RS] = 1.0f / exy;
}

// ---------------------------------------------------------------------------
// GEMM tile, k-major weights, conflict-free interleaved rows.
// Thread (rt,ot): rt in [0,16) owns row-pairs (2rt+32j, 2rt+32j+1), j<4.
// ot owns outs ot*TO..ot*TO+TO-1. Weights: Wc[k][LDWC] k-major, broadcast
// float4 LDG, register double-buffered 2 k-steps ahead.
// ---------------------------------------------------------------------------
template<int K, int TO, int LDWC>
__device__ __forceinline__ void gemm_kmaj(const float* __restrict__ At,
                                          const float* __restrict__ Wc,
                                          const float* __restrict__ bg,
                                          float* __restrict__ Ct,
                                          int rt, int ot)
{
    constexpr int NW = TO / 4;
    float2 acc[4][TO];
    #pragma unroll
    for (int i = 0; i < TO; i++) {
        float bo = __ldg(bg + ot*TO + i);
        #pragma unroll
        for (int j = 0; j < 4; j++) acc[j][i] = make_float2(bo, bo);
    }
    const float* xb = At + 2*rt;
    const float* wp = Wc + ot*TO;

    float4 wA[NW], wB[NW];
    #pragma unroll
    for (int i = 0; i < NW; i++) {
        wA[i] = __ldg(reinterpret_cast<const float4*>(wp)           + i);
        wB[i] = __ldg(reinterpret_cast<const float4*>(wp + LDWC)    + i);
    }

    #pragma unroll 1
    for (int k = 0; k < K; k += 2) {
        // x for k, k+1 (8x LDS.64, conflict-free interleave)
        float2 x0[4], x1[4];
        #pragma unroll
        for (int j = 0; j < 4; j++) {
            x0[j] = *reinterpret_cast<const float2*>(xb + k*RS     + 32*j);
            x1[j] = *reinterpret_cast<const float2*>(xb + (k+1)*RS + 32*j);
        }
        // prefetch weights k+2, k+3 (clamped; dead on last iter)
        int k2 = (k + 2 < K) ? k + 2 : 0;
        int k3 = (k + 3 < K) ? k + 3 : 0;
        float4 tA[NW], tB[NW];
        #pragma unroll
        for (int i = 0; i < NW; i++) {
            tA[i] = __ldg(reinterpret_cast<const float4*>(wp + k2*LDWC) + i);
            tB[i] = __ldg(reinterpret_cast<const float4*>(wp + k3*LDWC) + i);
        }

        const float* wAs = reinterpret_cast<const float*>(wA);
        #pragma unroll
        for (int i = 0; i < TO; i++) {
            float2 ws = make_float2(wAs[i], wAs[i]);
            acc[0][i] = ffma2(x0[0], ws, acc[0][i]);
            acc[1][i] = ffma2(x0[1], ws, acc[1][i]);
            acc[2][i] = ffma2(x0[2], ws, acc[2][i]);
            acc[3][i] = ffma2(x0[3], ws, acc[3][i]);
        }
        const float* wBs = reinterpret_cast<const float*>(wB);
        #pragma unroll
        for (int i = 0; i < TO; i++) {
            float2 ws = make_float2(wBs[i], wBs[i]);
            acc[0][i] = ffma2(x1[0], ws, acc[0][i]);
            acc[1][i] = ffma2(x1[1], ws, acc[1][i]);
            acc[2][i] = ffma2(x1[2], ws, acc[2][i]);
            acc[3][i] = ffma2(x1[3], ws, acc[3][i]);
        }
        #pragma unroll
        for (int i = 0; i < NW; i++) { wA[i] = tA[i]; wB[i] = tB[i]; }
    }

    // epilogue: leaky + float2 stores (interleaved rows, conflict-free)
    #pragma unroll
    for (int i = 0; i < TO; i++) {
        #pragma unroll
        for (int j = 0; j < 4; j++) {
            float2 v = acc[j][i];
            v.x = leaky_f(v.x);
            v.y = leaky_f(v.y);
            *reinterpret_cast<float2*>(Ct + (ot*TO + i)*RS + 2*rt + 32*j) = v;
        }
    }
}

// smem layout
#define SM_R0   (128*RS)
#define SM_R1   (256*RS)
#define SM_EN   (SM_R0 + SM_R1)
#define SM_LG   (SM_EN + 256)
#define SM_TOT  (SM_LG + 128)

#define EN_BLOCKS (NBATCH/2)

__global__ void __launch_bounds__(512, 1)
fused_kernel(const float* __restrict__ ego_y,
             const float* __restrict__ Pn,  const float* __restrict__ Pego,
             const float* __restrict__ Vn,  const float* __restrict__ Vego,
             const float* __restrict__ Cn,
             const float* __restrict__ W_sel, const float* __restrict__ b_sel,
             const float* __restrict__ W_s0,  const float* __restrict__ b_s0,
             const float* __restrict__ W_map, const float* __restrict__ b_map,
             const float* __restrict__ W_efc, const float* __restrict__ b_efc,
             const float* __restrict__ W_s1, const float* __restrict__ b_s1,
             const float* __restrict__ b1,
             const float* __restrict__ b2,
             const float* __restrict__ W3,  const float* __restrict__ b3,
             const float* __restrict__ Ww,  const float* __restrict__ bw,
             float* __restrict__ out)
{
    extern __shared__ float sm[];
    int tid = threadIdx.x;
    int blk = blockIdx.x;

    // =======================================================================
    // Er head blocks
    // =======================================================================
    if (blk >= EN_BLOCKS) {
        if (tid < 256) {
            int b = (blk - EN_BLOCKS) * 256 + tid;
            float ey = ego_y[b];
            float dy[4] = { 13.55f - ey, 17.45f - ey, 21.12f - ey, 24.91f - ey };

            float z[4];
            #pragma unroll
            for (int o = 0; o < 4; o++) {
                float a = __ldg(b_sel + o);
                #pragma unroll
                for (int i = 0; i < 4; i++) a = fmaf(dy[i], __ldg(W_sel + o*4+i), a);
                z[o] = a;
            }
            float m = fmaxf(fmaxf(z[0], z[1]), fmaxf(z[2], z[3]));
            float e[4], ssum = 0.f;
            #pragma unroll
            for (int i = 0; i < 4; i++) { e[i] = expf(z[i] - m); ssum += e[i]; }
            float x[4];
            #pragma unroll
            for (int i = 0; i < 4; i++) x[i] = (e[i] / ssum) * dy[i];

            float f[48];
            #pragma unroll
            for (int i = 0; i < 4; i++) f[i] = x[i];
            #pragma unroll
            for (int j = 0; j < 8; j++) {
                float arg = __ldg(b_s0 + j);
                #pragma unroll
                for (int i = 0; i < 4; i++) arg = fmaf(x[i], __ldg(W_s0 + j*4+i), arg);
                float s = my_sinf(arg) + EPSF;
                f[4 + j] = s;
                f[28 + j] = 1.0f / s;
            }
            #pragma unroll
            for (int i = 0; i < 4; i++) {
                float sq = x[i]*x[i] + EPSF;
                float cb = x[i]*x[i]*x[i] + EPSF;
                float ex = expf(x[i]) + EPSF;
                f[12+i] = sq;           f[36+i] = 1.0f / sq;
                f[16+i] = cb;           f[40+i] = 1.0f / cb;
                f[20+i] = ex;           f[44+i] = 1.0f / ex;
                f[24+i] = 1.0f / (x[i] + EPSF);
            }
            float y[8];
            #pragma unroll
            for (int o = 0; o < 8; o++) {
                float a = __ldg(b_map + o);
                #pragma unroll
                for (int k = 0; k < 48; k++) a = fmaf(f[k], __ldg(W_map + o*48+k), a);
                y[o] = leaky_f(a);
            }
            float r0 = __ldg(b_efc), r1 = __ldg(b_efc + 1);
            #pragma unroll
            for (int k = 0; k < 8; k++) {
                r0 = fmaf(y[k], __ldg(W_efc + k),     r0);
                r1 = fmaf(y[k], __ldg(W_efc + 8 + k), r1);
            }
            out[b*4 + 0] = r0;
            out[b*4 + 1] = r1;
        }
        return;
    }

    // =======================================================================
    // En blocks: 128 rows (2 batches x 64 neighbors)
    // =======================================================================
    float* At  = sm;              // features (transposed), later h2_T
    float* h1T = sm + SM_R0;      // h1, then layer3 partial scratch
    float* enb = sm + SM_EN;
    float* lgb = sm + SM_LG;

    // ---- phase 0: features ----
    if (tid < 256) {
        int r = tid >> 1;
        int part = tid & 1;
        int b = blk*2 + (r >> 6);
        int n = r & 63;
        int idx2 = (b*64 + n) * 2;
        float* Acol = At + r;
        if (part == 0) {
            float pex = Pego[b*2], pey = Pego[b*2+1];
            float pnx = Pn[idx2],  pny = Pn[idx2+1];
            float dx = pnx - pex,  dy = pny - pey;
            Acol[0*RS] = pex;  Acol[1*RS] = pey;
            Acol[2*RS] = pnx;  Acol[3*RS] = pny;
            Acol[4*RS] = dx;   Acol[5*RS] = dy;
            write_aug(Acol, 6, dx, dy, W_s1, b_s1);
            Acol[112*RS] = Cn[idx2];
            Acol[113*RS] = Cn[idx2+1];
        } else {
            float vex = Vego[b*2], vey = Vego[b*2+1];
            float vnx = Vn[idx2],  vny = Vn[idx2+1];
            float dx = vnx - vex,  dy = vny - vey;
            Acol[56*RS] = vex;  Acol[57*RS] = vey;
            Acol[58*RS] = vnx;  Acol[59*RS] = vny;
            Acol[60*RS] = dx;   Acol[61*RS] = dy;
            write_aug(Acol, 62, dx, dy, W_s1, b_s1);
        }
    }
    __syncthreads();

    int rt = tid & 15;
    int ot = tid >> 4;

    // ---- layer1: [128,114] -> [128,256], leaky ----
    gemm_kmaj<114, 8, 256>(At, g_W1c, b1, h1T, rt, ot);
    __syncthreads();

    // ---- layer2: [128,256] -> [128,128], leaky ----
    gemm_kmaj<256, 4, 128>(h1T, g_W2c, b2, At, rt, ot);
    __syncthreads();

    // ---- layer3: all 512 threads (4 k-segments x 128 rows) ----
    {
        int seg = tid >> 7;
        int r   = tid & 127;
        int k0  = seg * 32;
        float a0 = 0.f, a1 = 0.f;
        #pragma unroll 8
        for (int k = k0; k < k0 + 32; k++) {
            float h = At[k*RS + r];
            a0 = fmaf(h, __ldg(W3 + k),       a0);
            a1 = fmaf(h, __ldg(W3 + 128 + k), a1);
        }
        h1T[(seg*128 + r)*2]     = a0;
        h1T[(seg*128 + r)*2 + 1] = a1;
    }
    __syncthreads();

    // ---- layer3 reduce + logits ----
    if (tid < 128) {
        int r = tid;
        float a0 = __ldg(b3), a1 = __ldg(b3 + 1);
        #pragma unroll
        for (int seg = 0; seg < 4; seg++) {
            a0 += h1T[(seg*128 + r)*2];
            a1 += h1T[(seg*128 + r)*2 + 1];
        }
        enb[r*2]   = a0;
        enb[r*2+1] = a1;
        int b = blk*2 + (r >> 6);
        int n = r & 63;
        int idx2 = (b*64 + n) * 2;
        float pnx = Pn[idx2], pny = Pn[idx2+1];
        float dx = pnx - Pego[b*2], dy = pny - Pego[b*2+1];
        float lg = __ldg(bw);
        lg = fmaf(__ldg(Ww+0), a0,  lg);
        lg = fmaf(__ldg(Ww+1), a1,  lg);
        lg = fmaf(__ldg(Ww+2), pnx, lg);
        lg = fmaf(__ldg(Ww+3), pny, lg);
        lg = fmaf(__ldg(Ww+4), dx,  lg);
        lg = fmaf(__ldg(Ww+5), dy,  lg);
        lgb[r] = lg;
    }
    __syncthreads();

    // ---- softmax over 64 neighbors + weighted sum ----
    if (tid < 64) {
        int w = tid >> 5, l = tid & 31;
        int base = w * 64;
        float v0 = lgb[base + l], v1 = lgb[base + 32 + l];
        float m = fmaxf(v0, v1);
        #pragma unroll
        for (int off = 16; off; off >>= 1)
            m = fmaxf(m, __shfl_xor_sync(0xffffffffu, m, off));
        float e0 = expf(v0 - m), e1 = expf(v1 - m);
        float s  = e0 + e1;
        float n0 = e0 * enb[(base+l)*2]     + e1 * enb[(base+32+l)*2];
        float n1 = e0 * enb[(base+l)*2 + 1] + e1 * enb[(base+32+l)*2 + 1];
        #pragma unroll
        for (int off = 16; off; off >>= 1) {
            s  += __shfl_xor_sync(0xffffffffu, s,  off);
            n0 += __shfl_xor_sync(0xffffffffu, n0, off);
            n1 += __shfl_xor_sync(0xffffffffu, n1, off);
        }
        if (l == 0) {
            int b = blk*2 + w;
            out[b*4 + 2] = n0 / s;
            out[b*4 + 3] = n1 / s;
        }
    }
}

// ---------------------------------------------------------------------------
extern "C" void kernel_launch(void* const* d_in, const int* in_sizes, int n_in,
                              void* d_out, int out_size)
{
    const float* ego_y = (const float*)d_in[0];
    const float* Pn    = (const float*)d_in[1];
    const float* Pego  = (const float*)d_in[2];
    const float* Vn    = (const float*)d_in[3];
    const float* Vego  = (const float*)d_in[4];
    const float* Cn    = (const float*)d_in[5];
    const float* W_sel = (const float*)d_in[6];
    const float* b_sel = (const float*)d_in[7];
    const float* W_s0  = (const float*)d_in[8];
    const float* b_s0  = (const float*)d_in[9];
    const float* W_map = (const float*)d_in[10];
    const float* b_map = (const float*)d_in[11];
    const float* W_efc = (const float*)d_in[12];
    const float* b_efc = (const float*)d_in[13];
    const float* W_s1  = (const float*)d_in[14];
    const float* b_s1  = (const float*)d_in[15];
    const float* W1    = (const float*)d_in[16];
    const float* b1    = (const float*)d_in[17];
    const float* W2    = (const float*)d_in[18];
    const float* b2    = (const float*)d_in[19];
    const float* W3    = (const float*)d_in[20];
    const float* b3    = (const float*)d_in[21];
    const float* Ww    = (const float*)d_in[22];
    const float* bw    = (const float*)d_in[23];
    float* out = (float*)d_out;

    size_t smem_bytes = (size_t)SM_TOT * sizeof(float);
    cudaFuncSetAttribute(fused_kernel, cudaFuncAttributeMaxDynamicSharedMemorySize,
                         (int)smem_bytes);

    repack_kernel<<<128, 256>>>(W1, W2);
    fused_kernel<<<EN_BLOCKS + 16, 512, smem_bytes>>>(
        ego_y, Pn, Pego, Vn, Vego, Cn,
        W_sel, b_sel, W_s0, b_s0, W_map, b_map, W_efc, b_efc,
        W_s1, b_s1, b1, b2, W3, b3, Ww, bw, out);
}

// round 5
// speedup vs baseline: 1.5971x; 1.0471x over previous
#include <cuda_runtime.h>
#include <math.h>
#include <stdint.h>

#define EPSF 1e-6f
#define NBATCH 4096
#define RS 132            // padded row stride (layout [k][row]), mult of 4

// k-major repacked weights (+4 zero-padded rows for unconditional prefetch)
__device__ float g_W1c[(114 + 4) * 256];   // [k][out]
__device__ float g_W2c[(256 + 4) * 128];   // [k][out]

// ---------------------------------------------------------------------------
__device__ __forceinline__ float2 ffma2(float2 a, float2 b, float2 c) {
    float2 d;
    asm("fma.rn.f32x2 %0, %1, %2, %3;"
        : "=l"(reinterpret_cast<unsigned long long&>(d))
        : "l"(reinterpret_cast<unsigned long long&>(a)),
          "l"(reinterpret_cast<unsigned long long&>(b)),
          "l"(reinterpret_cast<unsigned long long&>(c)));
    return d;
}

__device__ __forceinline__ float my_sinf(float x) {
    float k = rintf(x * 0.318309886183790672f);
    float r = fmaf(k, -3.14159274101257324f, x);
    r = fmaf(k, 8.742278012618954e-8f, r);
    float r2 = r * r;
    float p = -2.50521083854e-08f;
    p = fmaf(p, r2, 2.75573192239e-06f);
    p = fmaf(p, r2, -1.98412698413e-04f);
    p = fmaf(p, r2, 8.33333333333e-03f);
    p = fmaf(p, r2, -1.66666666667e-01f);
    float s = fmaf(p * r2, r, r);
    int ki = __float2int_rn(k);
    return (ki & 1) ? -s : s;
}

__device__ __forceinline__ float leaky_f(float x) { return x >= 0.f ? x : 0.1f * x; }

// ---------------------------------------------------------------------------
// repack W1 [256,114] -> W1c [114+4,256]; W2 [128,256] -> W2c [256+4,128]
// (zero the pad rows so prefetch-past-end reads clean data)
// ---------------------------------------------------------------------------
__global__ void repack_kernel(const float* __restrict__ W1,
                              const float* __restrict__ W2)
{
    int idx = blockIdx.x * 256 + threadIdx.x;
    if (idx < (114 + 4) * 256) {
        int k = idx >> 8, o = idx & 255;
        g_W1c[idx] = (k < 114) ? W1[o * 114 + k] : 0.f;
    }
    if (idx < (256 + 4) * 128) {
        int k = idx >> 7, o = idx & 127;
        g_W2c[idx] = (k < 256) ? W2[o * 256 + k] : 0.f;
    }
}

// ---------------------------------------------------------------------------
// write one _auge block (50 features) into transposed smem column
// ---------------------------------------------------------------------------
__device__ __forceinline__ void write_aug(float* __restrict__ Acol, int base,
                                          float dx, float dy,
                                          const float* __restrict__ W_s1,
                                          const float* __restrict__ b_s1)
{
    Acol[(base+0)*RS] = dx;
    Acol[(base+1)*RS] = dy;
    #pragma unroll 1
    for (int j = 0; j < 17; j++) {
        float arg = fmaf(dx, __ldg(W_s1 + 2*j),
                    fmaf(dy, __ldg(W_s1 + 2*j + 1), __ldg(b_s1 + j)));
        float s = my_sinf(arg) + EPSF;
        Acol[(base+2+j)*RS]  = s;
        Acol[(base+27+j)*RS] = 1.0f / s;
    }
    float sqx = dx*dx + EPSF, sqy = dy*dy + EPSF;
    float cbx = dx*dx*dx + EPSF, cby = dy*dy*dy + EPSF;
    float exx = expf(dx) + EPSF, exy = expf(dy) + EPSF;
    Acol[(base+19)*RS] = sqx;  Acol[(base+20)*RS] = sqy;
    Acol[(base+21)*RS] = cbx;  Acol[(base+22)*RS] = cby;
    Acol[(base+23)*RS] = exx;  Acol[(base+24)*RS] = exy;
    Acol[(base+25)*RS] = 1.0f / (dx + EPSF);
    Acol[(base+26)*RS] = 1.0f / (dy + EPSF);
    Acol[(base+44)*RS] = 1.0f / sqx;  Acol[(base+45)*RS] = 1.0f / sqy;
    Acol[(base+46)*RS] = 1.0f / cbx;  Acol[(base+47)*RS] = 1.0f / cby;
    Acol[(base+48)*RS] = 1.0f / exx;  Acol[(base+49)*RS] = 1.0f / exy;
}

// ---------------------------------------------------------------------------
// GEMM tile, k-major weights, conflict-free LDS.128 row blocks.
// Thread (rt,ot): rt in [0,16) owns rows [4rt,4rt+4) and [4rt+64,4rt+68).
// ot owns outs ot*TO..ot*TO+TO-1. Weights: Wc[k][LDWC] k-major, broadcast
// float4 LDG, register double-buffered, unconditional prefetch (padded).
// ---------------------------------------------------------------------------
template<int K, int TO, int LDWC>
__device__ __forceinline__ void gemm_kmaj(const float* __restrict__ At,
                                          const float* __restrict__ Wc,
                                          const float* __restrict__ bg,
                                          float* __restrict__ Ct,
                                          int rt, int ot)
{
    constexpr int NW = TO / 4;
    float2 acc[4][TO];
    #pragma unroll
    for (int i = 0; i < TO; i++) {
        float bo = __ldg(bg + ot*TO + i);
        #pragma unroll
        for (int j = 0; j < 4; j++) acc[j][i] = make_float2(bo, bo);
    }
    const float* xk = At + 4*rt;
    const float* wp = Wc + ot*TO;
    const float* wk = wp + 2*LDWC;     // prefetch pointer (k+2)

    float4 wA[NW], wB[NW];
    #pragma unroll
    for (int i = 0; i < NW; i++) {
        wA[i] = __ldg(reinterpret_cast<const float4*>(wp)        + i);
        wB[i] = __ldg(reinterpret_cast<const float4*>(wp + LDWC) + i);
    }

    #pragma unroll 2
    for (int k = 0; k < K; k += 2) {
        // x for k, k+1: 4x LDS.128, conflict-free
        float4 xa0 = *reinterpret_cast<const float4*>(xk);
        float4 xa1 = *reinterpret_cast<const float4*>(xk + 64);
        float4 xb0 = *reinterpret_cast<const float4*>(xk + RS);
        float4 xb1 = *reinterpret_cast<const float4*>(xk + RS + 64);
        xk += 2*RS;

        // prefetch weights k+2, k+3 (unconditional; pad rows are zero)
        float4 tA[NW], tB[NW];
        #pragma unroll
        for (int i = 0; i < NW; i++) {
            tA[i] = __ldg(reinterpret_cast<const float4*>(wk)        + i);
            tB[i] = __ldg(reinterpret_cast<const float4*>(wk + LDWC) + i);
        }
        wk += 2*LDWC;

        float2 p0 = make_float2(xa0.x, xa0.y);
        float2 p1 = make_float2(xa0.z, xa0.w);
        float2 p2 = make_float2(xa1.x, xa1.y);
        float2 p3 = make_float2(xa1.z, xa1.w);
        const float* wAs = reinterpret_cast<const float*>(wA);
        #pragma unroll
        for (int i = 0; i < TO; i++) {
            float2 ws = make_float2(wAs[i], wAs[i]);
            acc[0][i] = ffma2(p0, ws, acc[0][i]);
            acc[1][i] = ffma2(p1, ws, acc[1][i]);
            acc[2][i] = ffma2(p2, ws, acc[2][i]);
            acc[3][i] = ffma2(p3, ws, acc[3][i]);
        }
        float2 q0 = make_float2(xb0.x, xb0.y);
        float2 q1 = make_float2(xb0.z, xb0.w);
        float2 q2 = make_float2(xb1.x, xb1.y);
        float2 q3 = make_float2(xb1.z, xb1.w);
        const float* wBs = reinterpret_cast<const float*>(wB);
        #pragma unroll
        for (int i = 0; i < TO; i++) {
            float2 ws = make_float2(wBs[i], wBs[i]);
            acc[0][i] = ffma2(q0, ws, acc[0][i]);
            acc[1][i] = ffma2(q1, ws, acc[1][i]);
            acc[2][i] = ffma2(q2, ws, acc[2][i]);
            acc[3][i] = ffma2(q3, ws, acc[3][i]);
        }
        #pragma unroll
        for (int i = 0; i < NW; i++) { wA[i] = tA[i]; wB[i] = tB[i]; }
    }

    // epilogue: leaky + 2x STS.128 per out (conflict-free)
    #pragma unroll
    for (int i = 0; i < TO; i++) {
        float4 v0, v1;
        v0.x = leaky_f(acc[0][i].x); v0.y = leaky_f(acc[0][i].y);
        v0.z = leaky_f(acc[1][i].x); v0.w = leaky_f(acc[1][i].y);
        v1.x = leaky_f(acc[2][i].x); v1.y = leaky_f(acc[2][i].y);
        v1.z = leaky_f(acc[3][i].x); v1.w = leaky_f(acc[3][i].y);
        float* cb = Ct + (ot*TO + i)*RS + 4*rt;
        *reinterpret_cast<float4*>(cb)      = v0;
        *reinterpret_cast<float4*>(cb + 64) = v1;
    }
}

// smem layout
#define SM_R0   (128*RS)
#define SM_R1   (256*RS)
#define SM_EN   (SM_R0 + SM_R1)
#define SM_LG   (SM_EN + 256)
#define SM_TOT  (SM_LG + 128)

#define EN_BLOCKS (NBATCH/2)

__global__ void __launch_bounds__(512, 1)
fused_kernel(const float* __restrict__ ego_y,
             const float* __restrict__ Pn,  const float* __restrict__ Pego,
             const float* __restrict__ Vn,  const float* __restrict__ Vego,
             const float* __restrict__ Cn,
             const float* __restrict__ W_sel, const float* __restrict__ b_sel,
             const float* __restrict__ W_s0,  const float* __restrict__ b_s0,
             const float* __restrict__ W_map, const float* __restrict__ b_map,
             const float* __restrict__ W_efc, const float* __restrict__ b_efc,
             const float* __restrict__ W_s1, const float* __restrict__ b_s1,
             const float* __restrict__ b1,
             const float* __restrict__ b2,
             const float* __restrict__ W3,  const float* __restrict__ b3,
             const float* __restrict__ Ww,  const float* __restrict__ bw,
             float* __restrict__ out)
{
    extern __shared__ float sm[];
    int tid = threadIdx.x;
    int blk = blockIdx.x;

    // =======================================================================
    // Er head blocks
    // =======================================================================
    if (blk >= EN_BLOCKS) {
        if (tid < 256) {
            int b = (blk - EN_BLOCKS) * 256 + tid;
            float ey = ego_y[b];
            float dy[4] = { 13.55f - ey, 17.45f - ey, 21.12f - ey, 24.91f - ey };

            float z[4];
            #pragma unroll
            for (int o = 0; o < 4; o++) {
                float a = __ldg(b_sel + o);
                #pragma unroll
                for (int i = 0; i < 4; i++) a = fmaf(dy[i], __ldg(W_sel + o*4+i), a);
                z[o] = a;
            }
            float m = fmaxf(fmaxf(z[0], z[1]), fmaxf(z[2], z[3]));
            float e[4], ssum = 0.f;
            #pragma unroll
            for (int i = 0; i < 4; i++) { e[i] = expf(z[i] - m); ssum += e[i]; }
            float x[4];
            #pragma unroll
            for (int i = 0; i < 4; i++) x[i] = (e[i] / ssum) * dy[i];

            float f[48];
            #pragma unroll
            for (int i = 0; i < 4; i++) f[i] = x[i];
            #pragma unroll
            for (int j = 0; j < 8; j++) {
                float arg = __ldg(b_s0 + j);
                #pragma unroll
                for (int i = 0; i < 4; i++) arg = fmaf(x[i], __ldg(W_s0 + j*4+i), arg);
                float s = my_sinf(arg) + EPSF;
                f[4 + j] = s;
                f[28 + j] = 1.0f / s;
            }
            #pragma unroll
            for (int i = 0; i < 4; i++) {
                float sq = x[i]*x[i] + EPSF;
                float cb = x[i]*x[i]*x[i] + EPSF;
                float ex = expf(x[i]) + EPSF;
                f[12+i] = sq;           f[36+i] = 1.0f / sq;
                f[16+i] = cb;           f[40+i] = 1.0f / cb;
                f[20+i] = ex;           f[44+i] = 1.0f / ex;
                f[24+i] = 1.0f / (x[i] + EPSF);
            }
            float y[8];
            #pragma unroll
            for (int o = 0; o < 8; o++) {
                float a = __ldg(b_map + o);
                #pragma unroll
                for (int k = 0; k < 48; k++) a = fmaf(f[k], __ldg(W_map + o*48+k), a);
                y[o] = leaky_f(a);
            }
            float r0 = __ldg(b_efc), r1 = __ldg(b_efc + 1);
            #pragma unroll
            for (int k = 0; k < 8; k++) {
                r0 = fmaf(y[k], __ldg(W_efc + k),     r0);
                r1 = fmaf(y[k], __ldg(W_efc + 8 + k), r1);
            }
            out[b*4 + 0] = r0;
            out[b*4 + 1] = r1;
        }
        return;
    }

    // =======================================================================
    // En blocks: 128 rows (2 batches x 64 neighbors)
    // =======================================================================
    float* At  = sm;              // features (transposed), later h2_T
    float* h1T = sm + SM_R0;      // h1, then layer3 partial scratch
    float* enb = sm + SM_EN;
    float* lgb = sm + SM_LG;

    // ---- phase 0: features ----
    if (tid < 256) {
        int r = tid >> 1;
        int part = tid & 1;
        int b = blk*2 + (r >> 6);
        int n = r & 63;
        int idx2 = (b*64 + n) * 2;
        float* Acol = At + r;
        if (part == 0) {
            float pex = Pego[b*2], pey = Pego[b*2+1];
            float pnx = Pn[idx2],  pny = Pn[idx2+1];
            float dx = pnx - pex,  dy = pny - pey;
            Acol[0*RS] = pex;  Acol[1*RS] = pey;
            Acol[2*RS] = pnx;  Acol[3*RS] = pny;
            Acol[4*RS] = dx;   Acol[5*RS] = dy;
            write_aug(Acol, 6, dx, dy, W_s1, b_s1);
            Acol[112*RS] = Cn[idx2];
            Acol[113*RS] = Cn[idx2+1];
        } else {
            float vex = Vego[b*2], vey = Vego[b*2+1];
            float vnx = Vn[idx2],  vny = Vn[idx2+1];
            float dx = vnx - vex,  dy = vny - vey;
            Acol[56*RS] = vex;  Acol[57*RS] = vey;
            Acol[58*RS] = vnx;  Acol[59*RS] = vny;
            Acol[60*RS] = dx;   Acol[61*RS] = dy;
            write_aug(Acol, 62, dx, dy, W_s1, b_s1);
        }
    }
    __syncthreads();

    int rt = tid & 15;
    int ot = tid >> 4;

    // ---- layer1: [128,114] -> [128,256], leaky ----
    gemm_kmaj<114, 8, 256>(At, g_W1c, b1, h1T, rt, ot);
    __syncthreads();

    // ---- layer2: [128,256] -> [128,128], leaky ----
    gemm_kmaj<256, 4, 128>(h1T, g_W2c, b2, At, rt, ot);
    __syncthreads();

    // ---- layer3: all 512 threads (4 k-segments x 128 rows) ----
    {
        int seg = tid >> 7;
        int r   = tid & 127;
        int k0  = seg * 32;
        float a0 = 0.f, a1 = 0.f;
        #pragma unroll 8
        for (int k = k0; k < k0 + 32; k++) {
            float h = At[k*RS + r];
            a0 = fmaf(h, __ldg(W3 + k),       a0);
            a1 = fmaf(h, __ldg(W3 + 128 + k), a1);
        }
        h1T[(seg*128 + r)*2]     = a0;
        h1T[(seg*128 + r)*2 + 1] = a1;
    }
    __syncthreads();

    // ---- layer3 reduce + logits ----
    if (tid < 128) {
        int r = tid;
        float a0 = __ldg(b3), a1 = __ldg(b3 + 1);
        #pragma unroll
        for (int seg = 0; seg < 4; seg++) {
            a0 += h1T[(seg*128 + r)*2];
            a1 += h1T[(seg*128 + r)*2 + 1];
        }
        enb[r*2]   = a0;
        enb[r*2+1] = a1;
        int b = blk*2 + (r >> 6);
        int n = r & 63;
        int idx2 = (b*64 + n) * 2;
        float pnx = Pn[idx2], pny = Pn[idx2+1];
        float dx = pnx - Pego[b*2], dy = pny - Pego[b*2+1];
        float lg = __ldg(bw);
        lg = fmaf(__ldg(Ww+0), a0,  lg);
        lg = fmaf(__ldg(Ww+1), a1,  lg);
        lg = fmaf(__ldg(Ww+2), pnx, lg);
        lg = fmaf(__ldg(Ww+3), pny, lg);
        lg = fmaf(__ldg(Ww+4), dx,  lg);
        lg = fmaf(__ldg(Ww+5), dy,  lg);
        lgb[r] = lg;
    }
    __syncthreads();

    // ---- softmax over 64 neighbors + weighted sum ----
    if (tid < 64) {
        int w = tid >> 5, l = tid & 31;
        int base = w * 64;
        float v0 = lgb[base + l], v1 = lgb[base + 32 + l];
        float m = fmaxf(v0, v1);
        #pragma unroll
        for (int off = 16; off; off >>= 1)
            m = fmaxf(m, __shfl_xor_sync(0xffffffffu, m, off));
        float e0 = expf(v0 - m), e1 = expf(v1 - m);
        float s  = e0 + e1;
        float n0 = e0 * enb[(base+l)*2]     + e1 * enb[(base+32+l)*2];
        float n1 = e0 * enb[(base+l)*2 + 1] + e1 * enb[(base+32+l)*2 + 1];
        #pragma unroll
        for (int off = 16; off; off >>= 1) {
            s  += __shfl_xor_sync(0xffffffffu, s,  off);
            n0 += __shfl_xor_sync(0xffffffffu, n0, off);
            n1 += __shfl_xor_sync(0xffffffffu, n1, off);
        }
        if (l == 0) {
            int b = blk*2 + w;
            out[b*4 + 2] = n0 / s;
            out[b*4 + 3] = n1 / s;
        }
    }
}

// ---------------------------------------------------------------------------
extern "C" void kernel_launch(void* const* d_in, const int* in_sizes, int n_in,
                              void* d_out, int out_size)
{
    const float* ego_y = (const float*)d_in[0];
    const float* Pn    = (const float*)d_in[1];
    const float* Pego  = (const float*)d_in[2];
    const float* Vn    = (const float*)d_in[3];
    const float* Vego  = (const float*)d_in[4];
    const float* Cn    = (const float*)d_in[5];
    const float* W_sel = (const float*)d_in[6];
    const float* b_sel = (const float*)d_in[7];
    const float* W_s0  = (const float*)d_in[8];
    const float* b_s0  = (const float*)d_in[9];
    const float* W_map = (const float*)d_in[10];
    const float* b_map = (const float*)d_in[11];
    const float* W_efc = (const float*)d_in[12];
    const float* b_efc = (const float*)d_in[13];
    const float* W_s1  = (const float*)d_in[14];
    const float* b_s1  = (const float*)d_in[15];
    const float* W1    = (const float*)d_in[16];
    const float* b1    = (const float*)d_in[17];
    const float* W2    = (const float*)d_in[18];
    const float* b2    = (const float*)d_in[19];
    const float* W3    = (const float*)d_in[20];
    const float* b3    = (const float*)d_in[21];
    const float* Ww    = (const float*)d_in[22];
    const float* bw    = (const float*)d_in[23];
    float* out = (float*)d_out;

    size_t smem_bytes = (size_t)SM_TOT * sizeof(float);
    cudaFuncSetAttribute(fused_kernel, cudaFuncAttributeMaxDynamicSharedMemorySize,
                         (int)smem_bytes);

    repack_kernel<<<130, 256>>>(W1, W2);
    fused_kernel<<<EN_BLOCKS + 16, 512, smem_bytes>>>(
        ego_y, Pn, Pego, Vn, Vego, Cn,
        W_sel, b_sel, W_s0, b_s0, W_map, b_map, W_efc, b_efc,
        W_s1, b_s1, b1, b2, W3, b3, Ww, bw, out);
}